// round 15
// baseline (speedup 1.0000x reference)
#include <cuda_runtime.h>
#include <cuda_bf16.h>
#include <math.h>
#include <stdint.h>

#define N_NODES 100000
#define N_EDGES 320000
#define N_GRAPHS 200
#define EMB 128
#define DD 256
#define STEPS 6
#define HID 128

typedef __nv_bfloat16 bf16;
typedef __nv_bfloat162 bf162;

#define BM 128
#define BN 128
#define BKH 64
#define PADH 72
#define GT  256
#define TBUFH (BM * PADH)
#define NSTG 3
#define GEMM_SMEM (2 * NSTG * TBUFH * 2)   // 110592 bytes

#define MR   ((N_NODES + BM - 1) / BM)   // 782
#define GHC  (MR * 6)
#define TOT  (GHC * 5 / 4 + 1)
#define SCC  (TOT / 5)

// ---------------- scratch (device globals; no allocations allowed) ----------
__device__ __align__(16) bf16 g_hb  [N_NODES * DD];
__device__ __align__(16) bf16 g_aggb[N_NODES * DD];
__device__ __align__(16) bf16 g_ghb [N_NODES * 3 * DD];
__device__ __align__(16) bf16 g_gib [N_NODES * 3 * DD];
__device__ __align__(16) bf16 g_xb  [N_NODES * EMB];
__device__ __align__(16) bf16 g_linwb[DD * EMB];
__device__ __align__(16) bf16 g_wihb[3 * DD * DD];
__device__ __align__(16) bf16 g_whhb[3 * DD * DD];
__device__ __align__(16) bf16 g_gwb [STEPS * DD * DD];
__device__ __align__(16) bf16 g_Qb  [3 * DD * STEPS * DD];   // [768, 1536]
__device__ __align__(16) float g_gsum[N_GRAPHS * DD];
__device__ __align__(16) float g_gcnt[N_GRAPHS];
__device__ int g_deg  [N_NODES];
__device__ int g_start[N_NODES];
__device__ int g_fill [N_NODES];
__device__ int g_srcl [N_EDGES];
__device__ int g_tcnt [STEPS * MR];      // per-(step,row-block) tile counters

__device__ __forceinline__ uint32_t smem_u32(const void* p) {
    uint32_t a;
    asm("{ .reg .u64 t; cvta.to.shared.u64 t, %1; cvt.u32.u64 %0, t; }" : "=r"(a) : "l"(p));
    return a;
}

__device__ __forceinline__ void cp16(uint32_t dst, const bf16* src) {
    asm volatile("cp.async.cg.shared.global [%0], [%1], 16;" :: "r"(dst), "l"(src));
}
__device__ __forceinline__ void cp16z(uint32_t dst, const bf16* src, int pred) {
    asm volatile("cp.async.cg.shared.global [%0], [%1], 16, %2;"
                 :: "r"(dst), "l"(src), "r"(pred ? 16 : 0));
}

#define LDSM_X4(r0, r1, r2, r3, addr) \
    asm volatile("ldmatrix.sync.aligned.m8n8.x4.shared.b16 {%0,%1,%2,%3}, [%4];" \
                 : "=r"(r0), "=r"(r1), "=r"(r2), "=r"(r3) : "r"(addr))

__device__ __forceinline__ void mma_bf16(float* d, const uint32_t* a, const uint32_t* b) {
    asm volatile(
        "mma.sync.aligned.m16n8k16.row.col.f32.bf16.bf16.f32 "
        "{%0,%1,%2,%3}, {%4,%5,%6,%7}, {%8,%9}, {%0,%1,%2,%3};"
        : "+f"(d[0]), "+f"(d[1]), "+f"(d[2]), "+f"(d[3])
        : "r"(a[0]), "r"(a[1]), "r"(a[2]), "r"(a[3]), "r"(b[0]), "r"(b[1]));
}

__device__ __forceinline__ void red_add_v4(float* addr, float4 v) {
    asm volatile("red.global.add.v4.f32 [%0], {%1, %2, %3, %4};"
                 :: "l"(addr), "f"(v.x), "f"(v.y), "f"(v.z), "f"(v.w) : "memory");
}

__device__ __forceinline__ float sigmoidf(float x) { return 1.f / (1.f + expf(-x)); }

// bf16 GEMM tile body: 128x128, m16n8k16, 3-stage cp.async ring, ldmatrix frags.
__device__ __forceinline__ void gemm_tile_body(
    const bf16* __restrict__ A, const bf16* __restrict__ B,
    const float* __restrict__ bias, bf16* __restrict__ C,
    int M, int K, int lda, int ldb, int ldc, int bm, int bn, bf16* sm)
{
    bf16* Asm = sm;
    bf16* Bsm = sm + NSTG * TBUFH;
    const uint32_t as0 = smem_u32(Asm);
    const uint32_t bs0 = smem_u32(Bsm);

    const int tid  = threadIdx.x;
    const int wid  = tid >> 5;
    const int lane = tid & 31;
    const int g    = lane >> 2;
    const int t4   = lane & 3;
    const int wm   = (wid >> 1) * 32;
    const int wn   = (wid & 1) * 64;
    const int KC   = K / BKH;

    const int m8 = lane >> 3;
    const int r8 = lane & 7;
    uint32_t aoff[2], boff[4];
#pragma unroll
    for (int i = 0; i < 2; i++)
        aoff[i] = ((wm + 16 * i + ((m8 & 1) << 3) + r8) * PADH + ((m8 & 2) << 2)) * 2;
#pragma unroll
    for (int jj = 0; jj < 4; jj++)
        boff[jj] = ((wn + 8 * (2 * jj + (m8 >> 1)) + r8) * PADH + ((m8 & 1) << 3)) * 2;

    float acc[2][8][4];
#pragma unroll
    for (int i = 0; i < 2; i++)
#pragma unroll
        for (int j = 0; j < 8; j++)
#pragma unroll
            for (int q = 0; q < 4; q++) acc[i][j][q] = 0.f;

    auto load_chunk = [&](int c, int buf) {
        const bf16* Ag = A + (size_t)bm * lda + c * BKH;
        const bf16* Bg = B + (size_t)bn * ldb + c * BKH;
        const uint32_t abase = as0 + buf * (TBUFH * 2);
        const uint32_t bbase = bs0 + buf * (TBUFH * 2);
#pragma unroll
        for (int i = 0; i < 4; i++) {
            int idx = tid + i * GT;
            int row = idx >> 3, f8 = idx & 7;
            cp16z(abase + (row * PADH + f8 * 8) * 2,
                  Ag + (size_t)row * lda + f8 * 8, (bm + row) < M);
        }
#pragma unroll
        for (int i = 0; i < 4; i++) {
            int idx = tid + i * GT;
            int row = idx >> 3, f8 = idx & 7;
            cp16(bbase + (row * PADH + f8 * 8) * 2,
                 Bg + (size_t)row * ldb + f8 * 8);
        }
        asm volatile("cp.async.commit_group;" ::: "memory");
    };

    load_chunk(0, 0);
    if (KC > 1) load_chunk(1, 1);
    for (int c = 0; c < KC; c++) {
        if (c + 2 < KC) load_chunk(c + 2, (c + 2) % NSTG);
        int pending = KC - 1 - c;
        if (pending >= 2)      asm volatile("cp.async.wait_group 2;" ::: "memory");
        else if (pending == 1) asm volatile("cp.async.wait_group 1;" ::: "memory");
        else                   asm volatile("cp.async.wait_group 0;" ::: "memory");
        __syncthreads();

        const uint32_t abase = as0 + (c % NSTG) * (TBUFH * 2);
        const uint32_t bbase = bs0 + (c % NSTG) * (TBUFH * 2);
#pragma unroll
        for (int ks = 0; ks < 4; ks++) {
            const uint32_t kb = ks * 32;
            uint32_t a[2][4], b[8][2];
#pragma unroll
            for (int i = 0; i < 2; i++)
                LDSM_X4(a[i][0], a[i][1], a[i][2], a[i][3], abase + aoff[i] + kb);
#pragma unroll
            for (int jj = 0; jj < 4; jj++)
                LDSM_X4(b[2 * jj][0], b[2 * jj][1], b[2 * jj + 1][0], b[2 * jj + 1][1],
                        bbase + boff[jj] + kb);
#pragma unroll
            for (int i = 0; i < 2; i++)
#pragma unroll
                for (int j = 0; j < 8; j++) mma_bf16(acc[i][j], a[i], b[j]);
        }
        __syncthreads();
    }

#pragma unroll
    for (int i = 0; i < 2; i++) {
        int r0 = bm + wm + 16 * i + g;
#pragma unroll
        for (int j = 0; j < 8; j++) {
            int col = bn + wn + 8 * j + t4 * 2;
            float2 bb = make_float2(0.f, 0.f);
            if (bias) bb = *(const float2*)(bias + col);
            if (r0 < M) {
                bf162 v = __float22bfloat162_rn(
                    make_float2(acc[i][j][0] + bb.x, acc[i][j][1] + bb.y));
                *(bf162*)&C[(size_t)r0 * ldc + col] = v;
            }
            if (r0 + 8 < M) {
                bf162 v = __float22bfloat162_rn(
                    make_float2(acc[i][j][2] + bb.x, acc[i][j][3] + bb.y));
                *(bf162*)&C[(size_t)(r0 + 8) * ldc + col] = v;
            }
        }
    }
}

__global__ __launch_bounds__(GT, 2)
void gemm_bf(const bf16* __restrict__ A, const bf16* __restrict__ B,
             const float* __restrict__ bias, bf16* __restrict__ C,
             int M, int K, int lda, int ldb, int ldc) {
    extern __shared__ __align__(16) bf16 smh[];
    gemm_tile_body(A, B, bias, C, M, K, lda, ldb, ldc,
                   blockIdx.y * BM, blockIdx.x * BN, smh);
}

// ===== combined: gh = h @ w_hh^T + b_hh  OVERLAPPED WITH CSR gather(h) ======
__global__ __launch_bounds__(GT, 2)
void gh_gather(const bf16* __restrict__ h, const bf16* __restrict__ whh,
               const float* __restrict__ bhh, bf16* __restrict__ gh,
               const int* __restrict__ start, const int* __restrict__ deg,
               const int* __restrict__ srcl, bf16* __restrict__ agg) {
    extern __shared__ __align__(16) bf16 smh[];
    const int bid = blockIdx.x;
    if ((bid % 5) != 4) {
        int gid = bid - (bid + 1) / 5;
        if (gid >= GHC) return;
        int bm = (gid / 6) * BM;
        int bn = (gid % 6) * BN;
        gemm_tile_body(h, whh, bhh, gh, N_NODES, DD, DD, DD, 3 * DD, bm, bn, smh);
    } else {
        const int sid = bid / 5;
        const int total  = N_NODES * 32;
        const int stride = SCC * GT;
        for (int it = sid * GT + threadIdx.x; it < total; it += stride) {
            int n  = it >> 5;
            int c8 = (it & 31) << 3;
            int st = start[n];
            int en = st + deg[n];
            float acc[8];
#pragma unroll
            for (int q = 0; q < 8; q++) acc[q] = 0.f;
            for (int e = st; e < en; e++) {
                int s = srcl[e];
                uint4 raw = *(const uint4*)&h[(size_t)s * DD + c8];
                const bf162* p2 = (const bf162*)&raw;
#pragma unroll
                for (int q = 0; q < 4; q++) {
                    float2 f = __bfloat1622float2(p2[q]);
                    acc[2 * q] += f.x; acc[2 * q + 1] += f.y;
                }
            }
            uint4 outv;
            bf162* o2 = (bf162*)&outv;
#pragma unroll
            for (int q = 0; q < 4; q++)
                o2[q] = __float22bfloat162_rn(make_float2(acc[2 * q], acc[2 * q + 1]));
            *(uint4*)&agg[(size_t)n * DD + c8] = outv;
        }
    }
}

// ====== gi GEMM + overlapped GRU consumers (producer/consumer in one grid) ==
// bids in groups of 7 per row-block r: bids 7r..7r+5 = the 6 gi col-tiles,
// bid 7r+6 = GRU consumer (spins on cnt[r] == 6, then updates h rows).
__global__ __launch_bounds__(GT, 2)
void gi_gru_ol(const bf16* __restrict__ agg, const bf16* __restrict__ Bq,
               const float* __restrict__ bih, bf16* __restrict__ gi,
               const bf16* __restrict__ gh, bf16* __restrict__ h,
               int* __restrict__ cnt) {
    extern __shared__ __align__(16) bf16 smh[];
    const int bid = blockIdx.x;
    const int rb  = bid / 7;
    const int sl  = bid % 7;
    if (sl < 6) {
        // producer: gi col-tile sl of row-block rb
        gemm_tile_body(agg, Bq, bih, gi, N_NODES, DD,
                       DD, STEPS * DD, 3 * DD, rb * BM, sl * BN, smh);
        __threadfence();
        __syncthreads();
        if (threadIdx.x == 0) atomicAdd(&cnt[rb], 1);
    } else {
        // consumer: GRU for rows [rb*BM, rb*BM+BM)
        if (threadIdx.x == 0) {
            int v;
            do {
                asm volatile("ld.global.acquire.gpu.b32 %0, [%1];"
                             : "=r"(v) : "l"(cnt + rb));
            } while (v < 6);
        }
        __syncthreads();
        __threadfence();
        const int tid = threadIdx.x;
#pragma unroll 4
        for (int k = 0; k < 16; k++) {
            int idx = tid + k * GT;            // 0..4095 = 128 rows x 32 groups
            int n   = rb * BM + (idx >> 5);
            if (n >= N_NODES) continue;
            int d8  = (idx & 31) << 3;
            const bf16* gin = gi + (size_t)n * (3 * DD);
            const bf16* ghn = gh + (size_t)n * (3 * DD);
            uint4 vir = *(const uint4*)&gin[d8];
            uint4 viz = *(const uint4*)&gin[DD + d8];
            uint4 vin = *(const uint4*)&gin[2 * DD + d8];
            uint4 vhr = *(const uint4*)&ghn[d8];
            uint4 vhz = *(const uint4*)&ghn[DD + d8];
            uint4 vhn = *(const uint4*)&ghn[2 * DD + d8];
            uint4 vh  = *(const uint4*)&h[(size_t)n * DD + d8];
            const bf162* ir = (const bf162*)&vir;
            const bf162* iz = (const bf162*)&viz;
            const bf162* in_ = (const bf162*)&vin;
            const bf162* hr = (const bf162*)&vhr;
            const bf162* hz = (const bf162*)&vhz;
            const bf162* hn = (const bf162*)&vhn;
            const bf162* hv = (const bf162*)&vh;
            uint4 outv;
            bf162* o2 = (bf162*)&outv;
#pragma unroll
            for (int q = 0; q < 4; q++) {
                float2 fir = __bfloat1622float2(ir[q]), fhr = __bfloat1622float2(hr[q]);
                float2 fiz = __bfloat1622float2(iz[q]), fhz = __bfloat1622float2(hz[q]);
                float2 fin = __bfloat1622float2(in_[q]), fhn = __bfloat1622float2(hn[q]);
                float2 fh  = __bfloat1622float2(hv[q]);
                float r0 = sigmoidf(fir.x + fhr.x), z0 = sigmoidf(fiz.x + fhz.x);
                float n0 = tanhf(fin.x + r0 * fhn.x);
                float r1 = sigmoidf(fir.y + fhr.y), z1 = sigmoidf(fiz.y + fhz.y);
                float n1 = tanhf(fin.y + r1 * fhn.y);
                o2[q] = __float22bfloat162_rn(make_float2(
                    (1.f - z0) * n0 + z0 * fh.x, (1.f - z1) * n1 + z1 * fh.y));
            }
            *(uint4*)&h[(size_t)n * DD + d8] = outv;
        }
    }
}

// ---------------- CSR build (once per launch) --------------------------------
__global__ void zero_int(int* __restrict__ p, int n) {
    int i = blockIdx.x * blockDim.x + threadIdx.x;
    if (i < n) p[i] = 0;
}
__global__ void hist_k(const int* __restrict__ ei, int* __restrict__ deg) {
    int e = blockIdx.x * blockDim.x + threadIdx.x;
    if (e < N_EDGES) atomicAdd(&deg[ei[N_EDGES + e]], 1);
}
__global__ void scan_k(const int* __restrict__ deg, int* __restrict__ start,
                       int* __restrict__ fill) {
    __shared__ int part[1024];
    const int t = threadIdx.x;
    const int CH = (N_NODES + 1023) / 1024;
    int s = 0;
    for (int i = 0; i < CH; i++) {
        int idx = t * CH + i;
        if (idx < N_NODES) s += deg[idx];
    }
    part[t] = s;
    __syncthreads();
    for (int off = 1; off < 1024; off <<= 1) {
        int v = (t >= off) ? part[t - off] : 0;
        __syncthreads();
        part[t] += v;
        __syncthreads();
    }
    int run = (t > 0) ? part[t - 1] : 0;
    for (int i = 0; i < CH; i++) {
        int idx = t * CH + i;
        if (idx < N_NODES) {
            start[idx] = run;
            fill[idx]  = run;
            run += deg[idx];
        }
    }
}
__global__ void fill_k(const int* __restrict__ ei, int* __restrict__ fill,
                       int* __restrict__ srcl) {
    int e = blockIdx.x * blockDim.x + threadIdx.x;
    if (e < N_EDGES) {
        int d = ei[N_EDGES + e];
        int slot = atomicAdd(&fill[d], 1);
        srcl[slot] = ei[e];
    }
}

// ---------------- small helpers ---------------------------------------------
__global__ void convert8(const float* __restrict__ in, bf16* __restrict__ outp, int n8) {
    int i = blockIdx.x * blockDim.x + threadIdx.x;
    if (i >= n8) return;
    float4 a = *(const float4*)(in + i * 8);
    float4 b = *(const float4*)(in + i * 8 + 4);
    uint4 o;
    bf162* o2 = (bf162*)&o;
    o2[0] = __float22bfloat162_rn(make_float2(a.x, a.y));
    o2[1] = __float22bfloat162_rn(make_float2(a.z, a.w));
    o2[2] = __float22bfloat162_rn(make_float2(b.x, b.y));
    o2[3] = __float22bfloat162_rn(make_float2(b.z, b.w));
    *(uint4*)(outp + i * 8) = o;
}

__global__ void zero_kernel(float4* __restrict__ p, int n4) {
    int tid = blockIdx.x * blockDim.x + threadIdx.x;
    if (tid < n4) p[tid] = make_float4(0.f, 0.f, 0.f, 0.f);
}

__global__ void pool_sum(const bf16* __restrict__ h, const int* __restrict__ batch,
                         float* __restrict__ gsum) {
    int tid = blockIdx.x * blockDim.x + threadIdx.x;
    if (tid >= N_NODES * 32) return;
    int n  = tid >> 5;
    int c8 = (tid & 31) << 3;
    int g  = batch[n];
    uint4 raw = *(const uint4*)&h[(size_t)n * DD + c8];
    const bf162* p2 = (const bf162*)&raw;
    float2 f0 = __bfloat1622float2(p2[0]);
    float2 f1 = __bfloat1622float2(p2[1]);
    float2 f2 = __bfloat1622float2(p2[2]);
    float2 f3 = __bfloat1622float2(p2[3]);
    red_add_v4(&gsum[g * DD + c8],     make_float4(f0.x, f0.y, f1.x, f1.y));
    red_add_v4(&gsum[g * DD + c8 + 4], make_float4(f2.x, f2.y, f3.x, f3.y));
}

__global__ void pool_cnt(const int* __restrict__ batch, float* __restrict__ gcnt) {
    int n = blockIdx.x * blockDim.x + threadIdx.x;
    if (n < N_NODES) atomicAdd(&gcnt[batch[n]], 1.f);
}

__global__ void classifier(const float* __restrict__ gsum, const float* __restrict__ gcnt,
                           const float* __restrict__ w1, const float* __restrict__ b1,
                           const float* __restrict__ w2, const float* __restrict__ b2,
                           float* __restrict__ out) {
    int g = blockIdx.x, t = threadIdx.x;   // 128 threads
    __shared__ float repr[DD];
    __shared__ float red[HID];
    float inv = 1.f / fmaxf(gcnt[g], 1.f);
    repr[t]       = gsum[g * DD + t] * inv;
    repr[t + HID] = gsum[g * DD + t + HID] * inv;
    __syncthreads();
    float acc = b1[t];
    const float* w = w1 + t * DD;
#pragma unroll 8
    for (int k = 0; k < DD; k++) acc += repr[k] * w[k];
    red[t] = fmaxf(acc, 0.f) * w2[t];
    __syncthreads();
    for (int s = 64; s > 0; s >>= 1) {
        if (t < s) red[t] += red[t + s];
        __syncthreads();
    }
    if (t == 0) out[g] = 1.f / (1.f + expf(-(red[0] + b2[0])));
}

// ---------------- launch -----------------------------------------------------
static void run_gemm(const bf16* A, const bf16* B, const float* bias, bf16* C,
                     int M, int N, int K, int lda, int ldb, int ldc) {
    dim3 grid(N / BN, (M + BM - 1) / BM);
    gemm_bf<<<grid, GT, GEMM_SMEM>>>(A, B, bias, C, M, K, lda, ldb, ldc);
}

extern "C" void kernel_launch(void* const* d_in, const int* in_sizes, int n_in,
                              void* d_out, int out_size) {
    const float* x      = (const float*)d_in[0];
    const float* lin_w  = (const float*)d_in[1];
    const float* lin_b  = (const float*)d_in[2];
    const float* ggnn_w = (const float*)d_in[3];
    const float* w_ih   = (const float*)d_in[4];
    const float* w_hh   = (const float*)d_in[5];
    const float* b_ih   = (const float*)d_in[6];
    const float* b_hh   = (const float*)d_in[7];
    const float* cls_w1 = (const float*)d_in[8];
    const float* cls_b1 = (const float*)d_in[9];
    const float* cls_w2 = (const float*)d_in[10];
    const float* cls_b2 = (const float*)d_in[11];
    const int* edge_index = (const int*)d_in[12];
    const int* batch      = (const int*)d_in[13];
    float* out = (float*)d_out;

    bf16 *hb, *aggb, *ghb, *gib, *xb, *linwb, *wihb, *whhb, *gwb, *Qb;
    float *gsum, *gcnt;
    int *deg, *start, *fill, *srcl, *tcnt;
    cudaGetSymbolAddress((void**)&hb,    g_hb);
    cudaGetSymbolAddress((void**)&aggb,  g_aggb);
    cudaGetSymbolAddress((void**)&ghb,   g_ghb);
    cudaGetSymbolAddress((void**)&gib,   g_gib);
    cudaGetSymbolAddress((void**)&xb,    g_xb);
    cudaGetSymbolAddress((void**)&linwb, g_linwb);
    cudaGetSymbolAddress((void**)&wihb,  g_wihb);
    cudaGetSymbolAddress((void**)&whhb,  g_whhb);
    cudaGetSymbolAddress((void**)&gwb,   g_gwb);
    cudaGetSymbolAddress((void**)&Qb,    g_Qb);
    cudaGetSymbolAddress((void**)&gsum,  g_gsum);
    cudaGetSymbolAddress((void**)&gcnt,  g_gcnt);
    cudaGetSymbolAddress((void**)&deg,   g_deg);
    cudaGetSymbolAddress((void**)&start, g_start);
    cudaGetSymbolAddress((void**)&fill,  g_fill);
    cudaGetSymbolAddress((void**)&srcl,  g_srcl);
    cudaGetSymbolAddress((void**)&tcnt,  g_tcnt);

    cudaFuncSetAttribute(gemm_bf,   cudaFuncAttributeMaxDynamicSharedMemorySize, GEMM_SMEM);
    cudaFuncSetAttribute(gh_gather, cudaFuncAttributeMaxDynamicSharedMemorySize, GEMM_SMEM);
    cudaFuncSetAttribute(gi_gru_ol, cudaFuncAttributeMaxDynamicSharedMemorySize, GEMM_SMEM);

    // ---- CSR build + counter zero ----
    zero_int<<<(N_NODES + 255) / 256, 256>>>(deg, N_NODES);
    zero_int<<<(STEPS * MR + 255) / 256, 256>>>(tcnt, STEPS * MR);
    hist_k<<<(N_EDGES + 255) / 256, 256>>>(edge_index, deg);
    scan_k<<<1, 1024>>>(deg, start, fill);
    fill_k<<<(N_EDGES + 255) / 256, 256>>>(edge_index, fill, srcl);

    // ---- fp32 -> bf16 conversions ----
    convert8<<<(N_NODES * EMB / 8 + 255) / 256, 256>>>(x, xb, N_NODES * EMB / 8);
    convert8<<<(DD * EMB / 8 + 255) / 256, 256>>>(lin_w, linwb, DD * EMB / 8);
    convert8<<<(3 * DD * DD / 8 + 255) / 256, 256>>>(w_ih, wihb, 3 * DD * DD / 8);
    convert8<<<(3 * DD * DD / 8 + 255) / 256, 256>>>(w_hh, whhb, 3 * DD * DD / 8);
    convert8<<<(STEPS * DD * DD / 8 + 255) / 256, 256>>>(ggnn_w, gwb, STEPS * DD * DD / 8);

    // Q[j, s*256+p] = sum_k w_ih[j,k] * ggnn_w[s][p,k]
    run_gemm(wihb, gwb, nullptr, Qb, 3 * DD, STEPS * DD, DD, DD, DD, STEPS * DD);
    // h = x @ lin_w^T + lin_b
    run_gemm(xb, linwb, lin_b, hb, N_NODES, DD, EMB, EMB, EMB, DD);

    for (int s = 0; s < STEPS; s++) {
        // gh = h @ w_hh^T + b_hh  overlapped with  agg[n] = sum_{e: dst=n} h[src]
        gh_gather<<<TOT, GT, GEMM_SMEM>>>(hb, whhb, b_hh, ghb, start, deg, srcl, aggb);
        // gi = agg @ Q_s^T + b_ih  with GRU consumers overlapped in the same grid
        gi_gru_ol<<<MR * 7, GT, GEMM_SMEM>>>(aggb, Qb + s * DD, b_ih, gib, ghb, hb,
                                             tcnt + s * MR);
    }

    zero_kernel<<<(N_GRAPHS * DD / 4 + 255) / 256, 256>>>((float4*)gsum, N_GRAPHS * DD / 4);
    zero_kernel<<<1, 64>>>((float4*)gcnt, N_GRAPHS / 4);
    pool_sum<<<(N_NODES * 32 + 255) / 256, 256>>>(hb, batch, gsum);
    pool_cnt<<<(N_NODES + 255) / 256, 256>>>(batch, gcnt);
    classifier<<<N_GRAPHS, HID>>>(gsum, gcnt, cls_w1, cls_b1, cls_w2, cls_b2, out);
}

// round 16
// speedup vs baseline: 1.1880x; 1.1880x over previous
#include <cuda_runtime.h>
#include <cuda_bf16.h>
#include <math.h>
#include <stdint.h>

#define N_NODES 100000
#define N_EDGES 320000
#define N_GRAPHS 200
#define EMB 128
#define DD 256
#define STEPS 6
#define HID 128

typedef __nv_bfloat16 bf16;
typedef __nv_bfloat162 bf162;

#define BM 128
#define BN 128
#define BKH 64
#define PADH 72
#define GT  256
#define TBUFH (BM * PADH)
#define NSTG 3
#define GEMM_SMEM (2 * NSTG * TBUFH * 2)   // 110592 bytes

#define MR   ((N_NODES + BM - 1) / BM)   // 782
#define GHC  (MR * 6)
#define TOT  (GHC * 5 / 4 + 1)
#define SCC  (TOT / 5)
#define SCB  ((N_NODES + 255) / 256)     // 391 scan blocks

// ---------------- scratch (device globals; no allocations allowed) ----------
__device__ __align__(16) bf16 g_hb  [N_NODES * DD];
__device__ __align__(16) bf16 g_aggb[N_NODES * DD];
__device__ __align__(16) bf16 g_ghb [N_NODES * 3 * DD];
__device__ __align__(16) bf16 g_gib [N_NODES * 3 * DD];
__device__ __align__(16) bf16 g_xb  [N_NODES * EMB];
__device__ __align__(16) bf16 g_linwb[DD * EMB];
__device__ __align__(16) bf16 g_wihb[3 * DD * DD];
__device__ __align__(16) bf16 g_whhb[3 * DD * DD];
__device__ __align__(16) bf16 g_gwb [STEPS * DD * DD];
__device__ __align__(16) bf16 g_Qb  [3 * DD * STEPS * DD];   // [768, 1536]
__device__ __align__(16) float g_gsum[N_GRAPHS * DD];
__device__ __align__(16) float g_gcnt[N_GRAPHS];
__device__ int g_deg  [N_NODES];
__device__ int g_start[N_NODES];
__device__ int g_fill [N_NODES];
__device__ int g_srcl [N_EDGES];
__device__ int g_part [SCB];

__device__ __forceinline__ uint32_t smem_u32(const void* p) {
    uint32_t a;
    asm("{ .reg .u64 t; cvta.to.shared.u64 t, %1; cvt.u32.u64 %0, t; }" : "=r"(a) : "l"(p));
    return a;
}

__device__ __forceinline__ void cp16(uint32_t dst, const bf16* src) {
    asm volatile("cp.async.cg.shared.global [%0], [%1], 16;" :: "r"(dst), "l"(src));
}
__device__ __forceinline__ void cp16z(uint32_t dst, const bf16* src, int pred) {
    asm volatile("cp.async.cg.shared.global [%0], [%1], 16, %2;"
                 :: "r"(dst), "l"(src), "r"(pred ? 16 : 0));
}

#define LDSM_X4(r0, r1, r2, r3, addr) \
    asm volatile("ldmatrix.sync.aligned.m8n8.x4.shared.b16 {%0,%1,%2,%3}, [%4];" \
                 : "=r"(r0), "=r"(r1), "=r"(r2), "=r"(r3) : "r"(addr))

__device__ __forceinline__ void mma_bf16(float* d, const uint32_t* a, const uint32_t* b) {
    asm volatile(
        "mma.sync.aligned.m16n8k16.row.col.f32.bf16.bf16.f32 "
        "{%0,%1,%2,%3}, {%4,%5,%6,%7}, {%8,%9}, {%0,%1,%2,%3};"
        : "+f"(d[0]), "+f"(d[1]), "+f"(d[2]), "+f"(d[3])
        : "r"(a[0]), "r"(a[1]), "r"(a[2]), "r"(a[3]), "r"(b[0]), "r"(b[1]));
}

__device__ __forceinline__ void red_add_v4(float* addr, float4 v) {
    asm volatile("red.global.add.v4.f32 [%0], {%1, %2, %3, %4};"
                 :: "l"(addr), "f"(v.x), "f"(v.y), "f"(v.z), "f"(v.w) : "memory");
}

__device__ __forceinline__ float sigmoidf(float x) { return 1.f / (1.f + expf(-x)); }

// bf16 GEMM tile body: 128x128, m16n8k16, 3-stage cp.async ring, ldmatrix frags.
__device__ __forceinline__ void gemm_tile_body(
    const bf16* __restrict__ A, const bf16* __restrict__ B,
    const float* __restrict__ bias, bf16* __restrict__ C,
    int M, int K, int lda, int ldb, int ldc, int bm, int bn, bf16* sm)
{
    bf16* Asm = sm;
    bf16* Bsm = sm + NSTG * TBUFH;
    const uint32_t as0 = smem_u32(Asm);
    const uint32_t bs0 = smem_u32(Bsm);

    const int tid  = threadIdx.x;
    const int wid  = tid >> 5;
    const int lane = tid & 31;
    const int g    = lane >> 2;
    const int t4   = lane & 3;
    const int wm   = (wid >> 1) * 32;
    const int wn   = (wid & 1) * 64;
    const int KC   = K / BKH;

    const int m8 = lane >> 3;
    const int r8 = lane & 7;
    uint32_t aoff[2], boff[4];
#pragma unroll
    for (int i = 0; i < 2; i++)
        aoff[i] = ((wm + 16 * i + ((m8 & 1) << 3) + r8) * PADH + ((m8 & 2) << 2)) * 2;
#pragma unroll
    for (int jj = 0; jj < 4; jj++)
        boff[jj] = ((wn + 8 * (2 * jj + (m8 >> 1)) + r8) * PADH + ((m8 & 1) << 3)) * 2;

    float acc[2][8][4];
#pragma unroll
    for (int i = 0; i < 2; i++)
#pragma unroll
        for (int j = 0; j < 8; j++)
#pragma unroll
            for (int q = 0; q < 4; q++) acc[i][j][q] = 0.f;

    auto load_chunk = [&](int c, int buf) {
        const bf16* Ag = A + (size_t)bm * lda + c * BKH;
        const bf16* Bg = B + (size_t)bn * ldb + c * BKH;
        const uint32_t abase = as0 + buf * (TBUFH * 2);
        const uint32_t bbase = bs0 + buf * (TBUFH * 2);
#pragma unroll
        for (int i = 0; i < 4; i++) {
            int idx = tid + i * GT;
            int row = idx >> 3, f8 = idx & 7;
            cp16z(abase + (row * PADH + f8 * 8) * 2,
                  Ag + (size_t)row * lda + f8 * 8, (bm + row) < M);
        }
#pragma unroll
        for (int i = 0; i < 4; i++) {
            int idx = tid + i * GT;
            int row = idx >> 3, f8 = idx & 7;
            cp16(bbase + (row * PADH + f8 * 8) * 2,
                 Bg + (size_t)row * ldb + f8 * 8);
        }
        asm volatile("cp.async.commit_group;" ::: "memory");
    };

    load_chunk(0, 0);
    if (KC > 1) load_chunk(1, 1);
    for (int c = 0; c < KC; c++) {
        if (c + 2 < KC) load_chunk(c + 2, (c + 2) % NSTG);
        int pending = KC - 1 - c;
        if (pending >= 2)      asm volatile("cp.async.wait_group 2;" ::: "memory");
        else if (pending == 1) asm volatile("cp.async.wait_group 1;" ::: "memory");
        else                   asm volatile("cp.async.wait_group 0;" ::: "memory");
        __syncthreads();

        const uint32_t abase = as0 + (c % NSTG) * (TBUFH * 2);
        const uint32_t bbase = bs0 + (c % NSTG) * (TBUFH * 2);
#pragma unroll
        for (int ks = 0; ks < 4; ks++) {
            const uint32_t kb = ks * 32;
            uint32_t a[2][4], b[8][2];
#pragma unroll
            for (int i = 0; i < 2; i++)
                LDSM_X4(a[i][0], a[i][1], a[i][2], a[i][3], abase + aoff[i] + kb);
#pragma unroll
            for (int jj = 0; jj < 4; jj++)
                LDSM_X4(b[2 * jj][0], b[2 * jj][1], b[2 * jj + 1][0], b[2 * jj + 1][1],
                        bbase + boff[jj] + kb);
#pragma unroll
            for (int i = 0; i < 2; i++)
#pragma unroll
                for (int j = 0; j < 8; j++) mma_bf16(acc[i][j], a[i], b[j]);
        }
        __syncthreads();
    }

#pragma unroll
    for (int i = 0; i < 2; i++) {
        int r0 = bm + wm + 16 * i + g;
#pragma unroll
        for (int j = 0; j < 8; j++) {
            int col = bn + wn + 8 * j + t4 * 2;
            float2 bb = make_float2(0.f, 0.f);
            if (bias) bb = *(const float2*)(bias + col);
            if (r0 < M) {
                bf162 v = __float22bfloat162_rn(
                    make_float2(acc[i][j][0] + bb.x, acc[i][j][1] + bb.y));
                *(bf162*)&C[(size_t)r0 * ldc + col] = v;
            }
            if (r0 + 8 < M) {
                bf162 v = __float22bfloat162_rn(
                    make_float2(acc[i][j][2] + bb.x, acc[i][j][3] + bb.y));
                *(bf162*)&C[(size_t)(r0 + 8) * ldc + col] = v;
            }
        }
    }
}

__global__ __launch_bounds__(GT, 2)
void gemm_bf(const bf16* __restrict__ A, const bf16* __restrict__ B,
             const float* __restrict__ bias, bf16* __restrict__ C,
             int M, int K, int lda, int ldb, int ldc) {
    extern __shared__ __align__(16) bf16 smh[];
    gemm_tile_body(A, B, bias, C, M, K, lda, ldb, ldc,
                   blockIdx.y * BM, blockIdx.x * BN, smh);
}

// ===== combined: gh = h @ w_hh^T + b_hh  OVERLAPPED WITH CSR gather(h) ======
__global__ __launch_bounds__(GT, 2)
void gh_gather(const bf16* __restrict__ h, const bf16* __restrict__ whh,
               const float* __restrict__ bhh, bf16* __restrict__ gh,
               const int* __restrict__ start, const int* __restrict__ deg,
               const int* __restrict__ srcl, bf16* __restrict__ agg) {
    extern __shared__ __align__(16) bf16 smh[];
    const int bid = blockIdx.x;
    if ((bid % 5) != 4) {
        int gid = bid - (bid + 1) / 5;
        if (gid >= GHC) return;
        int bm = (gid / 6) * BM;
        int bn = (gid % 6) * BN;
        gemm_tile_body(h, whh, bhh, gh, N_NODES, DD, DD, DD, 3 * DD, bm, bn, smh);
    } else {
        const int sid = bid / 5;
        const int total  = N_NODES * 32;
        const int stride = SCC * GT;
        for (int it = sid * GT + threadIdx.x; it < total; it += stride) {
            int n  = it >> 5;
            int c8 = (it & 31) << 3;
            int st = start[n];
            int en = st + deg[n];
            float acc[8];
#pragma unroll
            for (int q = 0; q < 8; q++) acc[q] = 0.f;
            for (int e = st; e < en; e++) {
                int s = srcl[e];
                uint4 raw = *(const uint4*)&h[(size_t)s * DD + c8];
                const bf162* p2 = (const bf162*)&raw;
#pragma unroll
                for (int q = 0; q < 4; q++) {
                    float2 f = __bfloat1622float2(p2[q]);
                    acc[2 * q] += f.x; acc[2 * q + 1] += f.y;
                }
            }
            uint4 outv;
            bf162* o2 = (bf162*)&outv;
#pragma unroll
            for (int q = 0; q < 4; q++)
                o2[q] = __float22bfloat162_rn(make_float2(acc[2 * q], acc[2 * q + 1]));
            *(uint4*)&agg[(size_t)n * DD + c8] = outv;
        }
    }
}

// ---------------- CSR build (once per launch; 3-phase parallel scan) ---------
__global__ void zero_int(int* __restrict__ p, int n) {
    int i = blockIdx.x * blockDim.x + threadIdx.x;
    if (i < n) p[i] = 0;
}
__global__ void hist_k(const int* __restrict__ ei, int* __restrict__ deg) {
    int e = blockIdx.x * blockDim.x + threadIdx.x;
    if (e < N_EDGES) atomicAdd(&deg[ei[N_EDGES + e]], 1);
}
// phase A: per-block sums of deg
__global__ void scan_part(const int* __restrict__ deg, int* __restrict__ part) {
    __shared__ int s[256];
    int i = blockIdx.x * 256 + threadIdx.x;
    s[threadIdx.x] = (i < N_NODES) ? deg[i] : 0;
    __syncthreads();
    for (int off = 128; off > 0; off >>= 1) {
        if (threadIdx.x < off) s[threadIdx.x] += s[threadIdx.x + off];
        __syncthreads();
    }
    if (threadIdx.x == 0) part[blockIdx.x] = s[0];
}
// phase B: exclusive scan of the SCB partials (single small block)
__global__ void scan_base(int* __restrict__ part) {
    __shared__ int s[512];
    int t = threadIdx.x;
    int v = (t < SCB) ? part[t] : 0;
    s[t] = v;
    __syncthreads();
    for (int off = 1; off < 512; off <<= 1) {
        int u = (t >= off) ? s[t - off] : 0;
        __syncthreads();
        s[t] += u;
        __syncthreads();
    }
    if (t < SCB) part[t] = s[t] - v;   // exclusive
}
// phase C: local inclusive scan + base -> exclusive start/fill
__global__ void scan_final(const int* __restrict__ deg, const int* __restrict__ part,
                           int* __restrict__ start, int* __restrict__ fill) {
    __shared__ int s[256];
    int i = blockIdx.x * 256 + threadIdx.x;
    int v = (i < N_NODES) ? deg[i] : 0;
    s[threadIdx.x] = v;
    __syncthreads();
    for (int off = 1; off < 256; off <<= 1) {
        int u = (threadIdx.x >= off) ? s[threadIdx.x - off] : 0;
        __syncthreads();
        s[threadIdx.x] += u;
        __syncthreads();
    }
    if (i < N_NODES) {
        int ex = part[blockIdx.x] + s[threadIdx.x] - v;
        start[i] = ex;
        fill[i]  = ex;
    }
}
__global__ void fill_k(const int* __restrict__ ei, int* __restrict__ fill,
                       int* __restrict__ srcl) {
    int e = blockIdx.x * blockDim.x + threadIdx.x;
    if (e < N_EDGES) {
        int d = ei[N_EDGES + e];
        int slot = atomicAdd(&fill[d], 1);
        srcl[slot] = ei[e];
    }
}

// ---------------- small helpers ---------------------------------------------
__global__ void convert8(const float* __restrict__ in, bf16* __restrict__ outp, int n8) {
    int i = blockIdx.x * blockDim.x + threadIdx.x;
    if (i >= n8) return;
    float4 a = *(const float4*)(in + i * 8);
    float4 b = *(const float4*)(in + i * 8 + 4);
    uint4 o;
    bf162* o2 = (bf162*)&o;
    o2[0] = __float22bfloat162_rn(make_float2(a.x, a.y));
    o2[1] = __float22bfloat162_rn(make_float2(a.z, a.w));
    o2[2] = __float22bfloat162_rn(make_float2(b.x, b.y));
    o2[3] = __float22bfloat162_rn(make_float2(b.z, b.w));
    *(uint4*)(outp + i * 8) = o;
}

__global__ void zero_kernel(float4* __restrict__ p, int n4) {
    int tid = blockIdx.x * blockDim.x + threadIdx.x;
    if (tid < n4) p[tid] = make_float4(0.f, 0.f, 0.f, 0.f);
}

__global__ void gru_update(const bf16* __restrict__ gi, const bf16* __restrict__ gh,
                           bf16* __restrict__ h) {
    int tid = blockIdx.x * blockDim.x + threadIdx.x;
    if (tid >= N_NODES * 32) return;
    int n  = tid >> 5;
    int d8 = (tid & 31) << 3;
    const bf16* gin = gi + (size_t)n * (3 * DD);
    const bf16* ghn = gh + (size_t)n * (3 * DD);
    uint4 vir = *(const uint4*)&gin[d8];
    uint4 viz = *(const uint4*)&gin[DD + d8];
    uint4 vin = *(const uint4*)&gin[2 * DD + d8];
    uint4 vhr = *(const uint4*)&ghn[d8];
    uint4 vhz = *(const uint4*)&ghn[DD + d8];
    uint4 vhn = *(const uint4*)&ghn[2 * DD + d8];
    uint4 vh  = *(const uint4*)&h[(size_t)n * DD + d8];
    const bf162* ir = (const bf162*)&vir;
    const bf162* iz = (const bf162*)&viz;
    const bf162* in_ = (const bf162*)&vin;
    const bf162* hr = (const bf162*)&vhr;
    const bf162* hz = (const bf162*)&vhz;
    const bf162* hn = (const bf162*)&vhn;
    const bf162* hv = (const bf162*)&vh;
    uint4 outv;
    bf162* o2 = (bf162*)&outv;
#pragma unroll
    for (int q = 0; q < 4; q++) {
        float2 fir = __bfloat1622float2(ir[q]), fhr = __bfloat1622float2(hr[q]);
        float2 fiz = __bfloat1622float2(iz[q]), fhz = __bfloat1622float2(hz[q]);
        float2 fin = __bfloat1622float2(in_[q]), fhn = __bfloat1622float2(hn[q]);
        float2 fh  = __bfloat1622float2(hv[q]);
        float r0 = sigmoidf(fir.x + fhr.x), z0 = sigmoidf(fiz.x + fhz.x);
        float n0 = tanhf(fin.x + r0 * fhn.x);
        float r1 = sigmoidf(fir.y + fhr.y), z1 = sigmoidf(fiz.y + fhz.y);
        float n1 = tanhf(fin.y + r1 * fhn.y);
        o2[q] = __float22bfloat162_rn(make_float2(
            (1.f - z0) * n0 + z0 * fh.x, (1.f - z1) * n1 + z1 * fh.y));
    }
    *(uint4*)&h[(size_t)n * DD + d8] = outv;
}

__global__ void pool_sum(const bf16* __restrict__ h, const int* __restrict__ batch,
                         float* __restrict__ gsum) {
    int tid = blockIdx.x * blockDim.x + threadIdx.x;
    if (tid >= N_NODES * 32) return;
    int n  = tid >> 5;
    int c8 = (tid & 31) << 3;
    int g  = batch[n];
    uint4 raw = *(const uint4*)&h[(size_t)n * DD + c8];
    const bf162* p2 = (const bf162*)&raw;
    float2 f0 = __bfloat1622float2(p2[0]);
    float2 f1 = __bfloat1622float2(p2[1]);
    float2 f2 = __bfloat1622float2(p2[2]);
    float2 f3 = __bfloat1622float2(p2[3]);
    red_add_v4(&gsum[g * DD + c8],     make_float4(f0.x, f0.y, f1.x, f1.y));
    red_add_v4(&gsum[g * DD + c8 + 4], make_float4(f2.x, f2.y, f3.x, f3.y));
}

__global__ void pool_cnt(const int* __restrict__ batch, float* __restrict__ gcnt) {
    int n = blockIdx.x * blockDim.x + threadIdx.x;
    if (n < N_NODES) atomicAdd(&gcnt[batch[n]], 1.f);
}

__global__ void classifier(const float* __restrict__ gsum, const float* __restrict__ gcnt,
                           const float* __restrict__ w1, const float* __restrict__ b1,
                           const float* __restrict__ w2, const float* __restrict__ b2,
                           float* __restrict__ out) {
    int g = blockIdx.x, t = threadIdx.x;   // 128 threads
    __shared__ float repr[DD];
    __shared__ float red[HID];
    float inv = 1.f / fmaxf(gcnt[g], 1.f);
    repr[t]       = gsum[g * DD + t] * inv;
    repr[t + HID] = gsum[g * DD + t + HID] * inv;
    __syncthreads();
    float acc = b1[t];
    const float* w = w1 + t * DD;
#pragma unroll 8
    for (int k = 0; k < DD; k++) acc += repr[k] * w[k];
    red[t] = fmaxf(acc, 0.f) * w2[t];
    __syncthreads();
    for (int s = 64; s > 0; s >>= 1) {
        if (t < s) red[t] += red[t + s];
        __syncthreads();
    }
    if (t == 0) out[g] = 1.f / (1.f + expf(-(red[0] + b2[0])));
}

// ---------------- launch -----------------------------------------------------
static void run_gemm(const bf16* A, const bf16* B, const float* bias, bf16* C,
                     int M, int N, int K, int lda, int ldb, int ldc) {
    dim3 grid(N / BN, (M + BM - 1) / BM);
    gemm_bf<<<grid, GT, GEMM_SMEM>>>(A, B, bias, C, M, K, lda, ldb, ldc);
}

extern "C" void kernel_launch(void* const* d_in, const int* in_sizes, int n_in,
                              void* d_out, int out_size) {
    const float* x      = (const float*)d_in[0];
    const float* lin_w  = (const float*)d_in[1];
    const float* lin_b  = (const float*)d_in[2];
    const float* ggnn_w = (const float*)d_in[3];
    const float* w_ih   = (const float*)d_in[4];
    const float* w_hh   = (const float*)d_in[5];
    const float* b_ih   = (const float*)d_in[6];
    const float* b_hh   = (const float*)d_in[7];
    const float* cls_w1 = (const float*)d_in[8];
    const float* cls_b1 = (const float*)d_in[9];
    const float* cls_w2 = (const float*)d_in[10];
    const float* cls_b2 = (const float*)d_in[11];
    const int* edge_index = (const int*)d_in[12];
    const int* batch      = (const int*)d_in[13];
    float* out = (float*)d_out;

    bf16 *hb, *aggb, *ghb, *gib, *xb, *linwb, *wihb, *whhb, *gwb, *Qb;
    float *gsum, *gcnt;
    int *deg, *start, *fill, *srcl, *part;
    cudaGetSymbolAddress((void**)&hb,    g_hb);
    cudaGetSymbolAddress((void**)&aggb,  g_aggb);
    cudaGetSymbolAddress((void**)&ghb,   g_ghb);
    cudaGetSymbolAddress((void**)&gib,   g_gib);
    cudaGetSymbolAddress((void**)&xb,    g_xb);
    cudaGetSymbolAddress((void**)&linwb, g_linwb);
    cudaGetSymbolAddress((void**)&wihb,  g_wihb);
    cudaGetSymbolAddress((void**)&whhb,  g_whhb);
    cudaGetSymbolAddress((void**)&gwb,   g_gwb);
    cudaGetSymbolAddress((void**)&Qb,    g_Qb);
    cudaGetSymbolAddress((void**)&gsum,  g_gsum);
    cudaGetSymbolAddress((void**)&gcnt,  g_gcnt);
    cudaGetSymbolAddress((void**)&deg,   g_deg);
    cudaGetSymbolAddress((void**)&start, g_start);
    cudaGetSymbolAddress((void**)&fill,  g_fill);
    cudaGetSymbolAddress((void**)&srcl,  g_srcl);
    cudaGetSymbolAddress((void**)&part,  g_part);

    cudaFuncSetAttribute(gemm_bf,   cudaFuncAttributeMaxDynamicSharedMemorySize, GEMM_SMEM);
    cudaFuncSetAttribute(gh_gather, cudaFuncAttributeMaxDynamicSharedMemorySize, GEMM_SMEM);

    // ---- CSR build (parallel 3-phase scan) ----
    zero_int<<<(N_NODES + 255) / 256, 256>>>(deg, N_NODES);
    hist_k<<<(N_EDGES + 255) / 256, 256>>>(edge_index, deg);
    scan_part<<<SCB, 256>>>(deg, part);
    scan_base<<<1, 512>>>(part);
    scan_final<<<SCB, 256>>>(deg, part, start, fill);
    fill_k<<<(N_EDGES + 255) / 256, 256>>>(edge_index, fill, srcl);

    // ---- fp32 -> bf16 conversions ----
    convert8<<<(N_NODES * EMB / 8 + 255) / 256, 256>>>(x, xb, N_NODES * EMB / 8);
    convert8<<<(DD * EMB / 8 + 255) / 256, 256>>>(lin_w, linwb, DD * EMB / 8);
    convert8<<<(3 * DD * DD / 8 + 255) / 256, 256>>>(w_ih, wihb, 3 * DD * DD / 8);
    convert8<<<(3 * DD * DD / 8 + 255) / 256, 256>>>(w_hh, whhb, 3 * DD * DD / 8);
    convert8<<<(STEPS * DD * DD / 8 + 255) / 256, 256>>>(ggnn_w, gwb, STEPS * DD * DD / 8);

    // Q[j, s*256+p] = sum_k w_ih[j,k] * ggnn_w[s][p,k]
    run_gemm(wihb, gwb, nullptr, Qb, 3 * DD, STEPS * DD, DD, DD, DD, STEPS * DD);
    // h = x @ lin_w^T + lin_b
    run_gemm(xb, linwb, lin_b, hb, N_NODES, DD, EMB, EMB, EMB, DD);

    for (int s = 0; s < STEPS; s++) {
        // gh = h @ w_hh^T + b_hh  overlapped with  agg[n] = sum_{e: dst=n} h[src]
        gh_gather<<<TOT, GT, GEMM_SMEM>>>(hb, whhb, b_hh, ghb, start, deg, srcl, aggb);
        // gi = agg @ Q_s^T + b_ih
        run_gemm(aggb, Qb + s * DD, b_ih, gib, N_NODES, 3 * DD, DD, DD, STEPS * DD, 3 * DD);
        gru_update<<<(N_NODES * 32 + 255) / 256, 256>>>(gib, ghb, hb);
    }

    zero_kernel<<<(N_GRAPHS * DD / 4 + 255) / 256, 256>>>((float4*)gsum, N_GRAPHS * DD / 4);
    zero_kernel<<<1, 64>>>((float4*)gcnt, N_GRAPHS / 4);
    pool_sum<<<(N_NODES * 32 + 255) / 256, 256>>>(hb, batch, gsum);
    pool_cnt<<<(N_NODES + 255) / 256, 256>>>(batch, gcnt);
    classifier<<<N_GRAPHS, HID>>>(gsum, gcnt, cls_w1, cls_b1, cls_w2, cls_b2, out);
}

// round 17
// speedup vs baseline: 1.1993x; 1.0095x over previous
#include <cuda_runtime.h>
#include <cuda_bf16.h>
#include <math.h>
#include <stdint.h>

#define N_NODES 100000
#define N_EDGES 320000
#define N_GRAPHS 200
#define EMB 128
#define DD 256
#define STEPS 6
#define HID 128

typedef __nv_bfloat16 bf16;
typedef __nv_bfloat162 bf162;

#define BM 128
#define BN 128
#define BKH 64
#define PADH 72
#define GT  256
#define TBUFH (BM * PADH)
#define NSTG 3
#define GEMM_SMEM (2 * NSTG * TBUFH * 2)   // 110592 bytes

#define MR   ((N_NODES + BM - 1) / BM)   // 782
#define GHC  (MR * 6)
#define RAT  6                            // every RAT-th CTA = gather
#define TOT  (GHC * RAT / (RAT - 1) + 1)
#define SCC  (TOT / RAT)
#define SCB  ((N_NODES + 255) / 256)     // 391 scan blocks

// ---------------- scratch (device globals; no allocations allowed) ----------
__device__ __align__(16) bf16 g_hb  [N_NODES * DD];
__device__ __align__(16) bf16 g_aggb[N_NODES * DD];
__device__ __align__(16) bf16 g_ghb [N_NODES * 3 * DD];
__device__ __align__(16) bf16 g_gib [N_NODES * 3 * DD];
__device__ __align__(16) bf16 g_xb  [N_NODES * EMB];
__device__ __align__(16) bf16 g_linwb[DD * EMB];
__device__ __align__(16) bf16 g_wihb[3 * DD * DD];
__device__ __align__(16) bf16 g_whhb[3 * DD * DD];
__device__ __align__(16) bf16 g_gwb [STEPS * DD * DD];
__device__ __align__(16) bf16 g_Qb  [3 * DD * STEPS * DD];   // [768, 1536]
__device__ __align__(16) float g_gsum[N_GRAPHS * DD];
__device__ __align__(16) float g_gcnt[N_GRAPHS];
__device__ int g_deg  [N_NODES];
__device__ int g_start[N_NODES];
__device__ int g_fill [N_NODES];
__device__ int g_srcl [N_EDGES];
__device__ int g_part [SCB];

__device__ __forceinline__ uint32_t smem_u32(const void* p) {
    uint32_t a;
    asm("{ .reg .u64 t; cvta.to.shared.u64 t, %1; cvt.u32.u64 %0, t; }" : "=r"(a) : "l"(p));
    return a;
}

__device__ __forceinline__ void cp16(uint32_t dst, const bf16* src) {
    asm volatile("cp.async.cg.shared.global [%0], [%1], 16;" :: "r"(dst), "l"(src));
}
__device__ __forceinline__ void cp16z(uint32_t dst, const bf16* src, int pred) {
    asm volatile("cp.async.cg.shared.global [%0], [%1], 16, %2;"
                 :: "r"(dst), "l"(src), "r"(pred ? 16 : 0));
}

#define LDSM_X4(r0, r1, r2, r3, addr) \
    asm volatile("ldmatrix.sync.aligned.m8n8.x4.shared.b16 {%0,%1,%2,%3}, [%4];" \
                 : "=r"(r0), "=r"(r1), "=r"(r2), "=r"(r3) : "r"(addr))

__device__ __forceinline__ void mma_bf16(float* d, const uint32_t* a, const uint32_t* b) {
    asm volatile(
        "mma.sync.aligned.m16n8k16.row.col.f32.bf16.bf16.f32 "
        "{%0,%1,%2,%3}, {%4,%5,%6,%7}, {%8,%9}, {%0,%1,%2,%3};"
        : "+f"(d[0]), "+f"(d[1]), "+f"(d[2]), "+f"(d[3])
        : "r"(a[0]), "r"(a[1]), "r"(a[2]), "r"(a[3]), "r"(b[0]), "r"(b[1]));
}

__device__ __forceinline__ void red_add_v4(float* addr, float4 v) {
    asm volatile("red.global.add.v4.f32 [%0], {%1, %2, %3, %4};"
                 :: "l"(addr), "f"(v.x), "f"(v.y), "f"(v.z), "f"(v.w) : "memory");
}

__device__ __forceinline__ float sigmoidf(float x) { return 1.f / (1.f + expf(-x)); }

// bf16 GEMM tile body: 128x128, m16n8k16, 3-stage cp.async ring, ldmatrix frags.
__device__ __forceinline__ void gemm_tile_body(
    const bf16* __restrict__ A, const bf16* __restrict__ B,
    const float* __restrict__ bias, bf16* __restrict__ C,
    int M, int K, int lda, int ldb, int ldc, int bm, int bn, bf16* sm)
{
    bf16* Asm = sm;
    bf16* Bsm = sm + NSTG * TBUFH;
    const uint32_t as0 = smem_u32(Asm);
    const uint32_t bs0 = smem_u32(Bsm);

    const int tid  = threadIdx.x;
    const int wid  = tid >> 5;
    const int lane = tid & 31;
    const int g    = lane >> 2;
    const int t4   = lane & 3;
    const int wm   = (wid >> 1) * 32;
    const int wn   = (wid & 1) * 64;
    const int KC   = K / BKH;

    const int m8 = lane >> 3;
    const int r8 = lane & 7;
    uint32_t aoff[2], boff[4];
#pragma unroll
    for (int i = 0; i < 2; i++)
        aoff[i] = ((wm + 16 * i + ((m8 & 1) << 3) + r8) * PADH + ((m8 & 2) << 2)) * 2;
#pragma unroll
    for (int jj = 0; jj < 4; jj++)
        boff[jj] = ((wn + 8 * (2 * jj + (m8 >> 1)) + r8) * PADH + ((m8 & 1) << 3)) * 2;

    float acc[2][8][4];
#pragma unroll
    for (int i = 0; i < 2; i++)
#pragma unroll
        for (int j = 0; j < 8; j++)
#pragma unroll
            for (int q = 0; q < 4; q++) acc[i][j][q] = 0.f;

    auto load_chunk = [&](int c, int buf) {
        const bf16* Ag = A + (size_t)bm * lda + c * BKH;
        const bf16* Bg = B + (size_t)bn * ldb + c * BKH;
        const uint32_t abase = as0 + buf * (TBUFH * 2);
        const uint32_t bbase = bs0 + buf * (TBUFH * 2);
#pragma unroll
        for (int i = 0; i < 4; i++) {
            int idx = tid + i * GT;
            int row = idx >> 3, f8 = idx & 7;
            cp16z(abase + (row * PADH + f8 * 8) * 2,
                  Ag + (size_t)row * lda + f8 * 8, (bm + row) < M);
        }
#pragma unroll
        for (int i = 0; i < 4; i++) {
            int idx = tid + i * GT;
            int row = idx >> 3, f8 = idx & 7;
            cp16(bbase + (row * PADH + f8 * 8) * 2,
                 Bg + (size_t)row * ldb + f8 * 8);
        }
        asm volatile("cp.async.commit_group;" ::: "memory");
    };

    load_chunk(0, 0);
    if (KC > 1) load_chunk(1, 1);
    for (int c = 0; c < KC; c++) {
        if (c + 2 < KC) load_chunk(c + 2, (c + 2) % NSTG);
        int pending = KC - 1 - c;
        if (pending >= 2)      asm volatile("cp.async.wait_group 2;" ::: "memory");
        else if (pending == 1) asm volatile("cp.async.wait_group 1;" ::: "memory");
        else                   asm volatile("cp.async.wait_group 0;" ::: "memory");
        __syncthreads();

        const uint32_t abase = as0 + (c % NSTG) * (TBUFH * 2);
        const uint32_t bbase = bs0 + (c % NSTG) * (TBUFH * 2);
#pragma unroll
        for (int ks = 0; ks < 4; ks++) {
            const uint32_t kb = ks * 32;
            uint32_t a[2][4], b[8][2];
#pragma unroll
            for (int i = 0; i < 2; i++)
                LDSM_X4(a[i][0], a[i][1], a[i][2], a[i][3], abase + aoff[i] + kb);
#pragma unroll
            for (int jj = 0; jj < 4; jj++)
                LDSM_X4(b[2 * jj][0], b[2 * jj][1], b[2 * jj + 1][0], b[2 * jj + 1][1],
                        bbase + boff[jj] + kb);
#pragma unroll
            for (int i = 0; i < 2; i++)
#pragma unroll
                for (int j = 0; j < 8; j++) mma_bf16(acc[i][j], a[i], b[j]);
        }
        __syncthreads();
    }

#pragma unroll
    for (int i = 0; i < 2; i++) {
        int r0 = bm + wm + 16 * i + g;
#pragma unroll
        for (int j = 0; j < 8; j++) {
            int col = bn + wn + 8 * j + t4 * 2;
            float2 bb = make_float2(0.f, 0.f);
            if (bias) bb = *(const float2*)(bias + col);
            if (r0 < M) {
                bf162 v = __float22bfloat162_rn(
                    make_float2(acc[i][j][0] + bb.x, acc[i][j][1] + bb.y));
                *(bf162*)&C[(size_t)r0 * ldc + col] = v;
            }
            if (r0 + 8 < M) {
                bf162 v = __float22bfloat162_rn(
                    make_float2(acc[i][j][2] + bb.x, acc[i][j][3] + bb.y));
                *(bf162*)&C[(size_t)(r0 + 8) * ldc + col] = v;
            }
        }
    }
}

__global__ __launch_bounds__(GT, 2)
void gemm_bf(const bf16* __restrict__ A, const bf16* __restrict__ B,
             const float* __restrict__ bias, bf16* __restrict__ C,
             int M, int K, int lda, int ldb, int ldc) {
    extern __shared__ __align__(16) bf16 smh[];
    gemm_tile_body(A, B, bias, C, M, K, lda, ldb, ldc,
                   blockIdx.y * BM, blockIdx.x * BN, smh);
}

// ===== combined: gh = h @ w_hh^T + b_hh  OVERLAPPED WITH CSR gather(h) ======
__global__ __launch_bounds__(GT, 2)
void gh_gather(const bf16* __restrict__ h, const bf16* __restrict__ whh,
               const float* __restrict__ bhh, bf16* __restrict__ gh,
               const int* __restrict__ start, const int* __restrict__ deg,
               const int* __restrict__ srcl, bf16* __restrict__ agg) {
    extern __shared__ __align__(16) bf16 smh[];
    const int bid = blockIdx.x;
    if ((bid % RAT) != (RAT - 1)) {
        int gid = bid - (bid + 1) / RAT;
        if (gid >= GHC) return;
        int bm = (gid / 6) * BM;
        int bn = (gid % 6) * BN;
        gemm_tile_body(h, whh, bhh, gh, N_NODES, DD, DD, DD, 3 * DD, bm, bn, smh);
    } else {
        const int sid = bid / RAT;
        const int total  = N_NODES * 32;
        const int stride = SCC * GT;
        for (int it = sid * GT + threadIdx.x; it < total; it += stride) {
            int n  = it >> 5;
            int c8 = (it & 31) << 3;
            int st = start[n];
            int en = st + deg[n];
            float acc[8];
#pragma unroll
            for (int q = 0; q < 8; q++) acc[q] = 0.f;
            for (int e = st; e < en; e++) {
                int s = srcl[e];
                uint4 raw = *(const uint4*)&h[(size_t)s * DD + c8];
                const bf162* p2 = (const bf162*)&raw;
#pragma unroll
                for (int q = 0; q < 4; q++) {
                    float2 f = __bfloat1622float2(p2[q]);
                    acc[2 * q] += f.x; acc[2 * q + 1] += f.y;
                }
            }
            uint4 outv;
            bf162* o2 = (bf162*)&outv;
#pragma unroll
            for (int q = 0; q < 4; q++)
                o2[q] = __float22bfloat162_rn(make_float2(acc[2 * q], acc[2 * q + 1]));
            *(uint4*)&agg[(size_t)n * DD + c8] = outv;
        }
    }
}

// ---------------- CSR build (once per launch; 3-phase parallel scan) ---------
__global__ void zero_int(int* __restrict__ p, int n) {
    int i = blockIdx.x * blockDim.x + threadIdx.x;
    if (i < n) p[i] = 0;
}
__global__ void hist_k(const int* __restrict__ ei, int* __restrict__ deg) {
    int e = blockIdx.x * blockDim.x + threadIdx.x;
    if (e < N_EDGES) atomicAdd(&deg[ei[N_EDGES + e]], 1);
}
__global__ void scan_part(const int* __restrict__ deg, int* __restrict__ part) {
    __shared__ int s[256];
    int i = blockIdx.x * 256 + threadIdx.x;
    s[threadIdx.x] = (i < N_NODES) ? deg[i] : 0;
    __syncthreads();
    for (int off = 128; off > 0; off >>= 1) {
        if (threadIdx.x < off) s[threadIdx.x] += s[threadIdx.x + off];
        __syncthreads();
    }
    if (threadIdx.x == 0) part[blockIdx.x] = s[0];
}
__global__ void scan_base(int* __restrict__ part) {
    __shared__ int s[512];
    int t = threadIdx.x;
    int v = (t < SCB) ? part[t] : 0;
    s[t] = v;
    __syncthreads();
    for (int off = 1; off < 512; off <<= 1) {
        int u = (t >= off) ? s[t - off] : 0;
        __syncthreads();
        s[t] += u;
        __syncthreads();
    }
    if (t < SCB) part[t] = s[t] - v;   // exclusive
}
__global__ void scan_final(const int* __restrict__ deg, const int* __restrict__ part,
                           int* __restrict__ start, int* __restrict__ fill) {
    __shared__ int s[256];
    int i = blockIdx.x * 256 + threadIdx.x;
    int v = (i < N_NODES) ? deg[i] : 0;
    s[threadIdx.x] = v;
    __syncthreads();
    for (int off = 1; off < 256; off <<= 1) {
        int u = (threadIdx.x >= off) ? s[threadIdx.x - off] : 0;
        __syncthreads();
        s[threadIdx.x] += u;
        __syncthreads();
    }
    if (i < N_NODES) {
        int ex = part[blockIdx.x] + s[threadIdx.x] - v;
        start[i] = ex;
        fill[i]  = ex;
    }
}
__global__ void fill_k(const int* __restrict__ ei, int* __restrict__ fill,
                       int* __restrict__ srcl) {
    int e = blockIdx.x * blockDim.x + threadIdx.x;
    if (e < N_EDGES) {
        int d = ei[N_EDGES + e];
        int slot = atomicAdd(&fill[d], 1);
        srcl[slot] = ei[e];
    }
}

// ---------------- batched fp32->bf16 conversion ------------------------------
// segments: x, lin_w, w_ih, w_hh, ggnn_w (element-8 groups)
#define CV_N0 (N_NODES * EMB / 8)
#define CV_N1 (DD * EMB / 8)
#define CV_N2 (3 * DD * DD / 8)
#define CV_N3 (3 * DD * DD / 8)
#define CV_N4 (STEPS * DD * DD / 8)
#define CV_TOTAL (CV_N0 + CV_N1 + CV_N2 + CV_N3 + CV_N4)

__global__ void convert_all(const float* __restrict__ s0, const float* __restrict__ s1,
                            const float* __restrict__ s2, const float* __restrict__ s3,
                            const float* __restrict__ s4,
                            bf16* __restrict__ d0, bf16* __restrict__ d1,
                            bf16* __restrict__ d2, bf16* __restrict__ d3,
                            bf16* __restrict__ d4) {
    int i = blockIdx.x * blockDim.x + threadIdx.x;
    if (i >= CV_TOTAL) return;
    const float* src; bf16* dst; int off;
    if (i < CV_N0)                      { src = s0; dst = d0; off = i; }
    else if (i < CV_N0 + CV_N1)         { src = s1; dst = d1; off = i - CV_N0; }
    else if (i < CV_N0 + CV_N1 + CV_N2) { src = s2; dst = d2; off = i - CV_N0 - CV_N1; }
    else if (i < CV_N0 + CV_N1 + CV_N2 + CV_N3)
                                        { src = s3; dst = d3; off = i - CV_N0 - CV_N1 - CV_N2; }
    else                                { src = s4; dst = d4; off = i - CV_N0 - CV_N1 - CV_N2 - CV_N3; }
    float4 a = *(const float4*)(src + off * 8);
    float4 b = *(const float4*)(src + off * 8 + 4);
    uint4 o;
    bf162* o2 = (bf162*)&o;
    o2[0] = __float22bfloat162_rn(make_float2(a.x, a.y));
    o2[1] = __float22bfloat162_rn(make_float2(a.z, a.w));
    o2[2] = __float22bfloat162_rn(make_float2(b.x, b.y));
    o2[3] = __float22bfloat162_rn(make_float2(b.z, b.w));
    *(uint4*)(dst + off * 8) = o;
}

// ---------------- small helpers ---------------------------------------------
__global__ void gru_update(const bf16* __restrict__ gi, const bf16* __restrict__ gh,
                           bf16* __restrict__ h) {
    int tid = blockIdx.x * blockDim.x + threadIdx.x;
    if (tid >= N_NODES * 32) return;
    int n  = tid >> 5;
    int d8 = (tid & 31) << 3;
    const bf16* gin = gi + (size_t)n * (3 * DD);
    const bf16* ghn = gh + (size_t)n * (3 * DD);
    uint4 vir = *(const uint4*)&gin[d8];
    uint4 viz = *(const uint4*)&gin[DD + d8];
    uint4 vin = *(const uint4*)&gin[2 * DD + d8];
    uint4 vhr = *(const uint4*)&ghn[d8];
    uint4 vhz = *(const uint4*)&ghn[DD + d8];
    uint4 vhn = *(const uint4*)&ghn[2 * DD + d8];
    uint4 vh  = *(const uint4*)&h[(size_t)n * DD + d8];
    const bf162* ir = (const bf162*)&vir;
    const bf162* iz = (const bf162*)&viz;
    const bf162* in_ = (const bf162*)&vin;
    const bf162* hr = (const bf162*)&vhr;
    const bf162* hz = (const bf162*)&vhz;
    const bf162* hn = (const bf162*)&vhn;
    const bf162* hv = (const bf162*)&vh;
    uint4 outv;
    bf162* o2 = (bf162*)&outv;
#pragma unroll
    for (int q = 0; q < 4; q++) {
        float2 fir = __bfloat1622float2(ir[q]), fhr = __bfloat1622float2(hr[q]);
        float2 fiz = __bfloat1622float2(iz[q]), fhz = __bfloat1622float2(hz[q]);
        float2 fin = __bfloat1622float2(in_[q]), fhn = __bfloat1622float2(hn[q]);
        float2 fh  = __bfloat1622float2(hv[q]);
        float r0 = sigmoidf(fir.x + fhr.x), z0 = sigmoidf(fiz.x + fhz.x);
        float n0 = tanhf(fin.x + r0 * fhn.x);
        float r1 = sigmoidf(fir.y + fhr.y), z1 = sigmoidf(fiz.y + fhz.y);
        float n1 = tanhf(fin.y + r1 * fhn.y);
        o2[q] = __float22bfloat162_rn(make_float2(
            (1.f - z0) * n0 + z0 * fh.x, (1.f - z1) * n1 + z1 * fh.y));
    }
    *(uint4*)&h[(size_t)n * DD + d8] = outv;
}

// zero gsum+gcnt in one launch
__global__ void zero_pool(float4* __restrict__ gsum4, float4* __restrict__ gcnt4) {
    int tid = blockIdx.x * blockDim.x + threadIdx.x;
    if (tid < N_GRAPHS * DD / 4) gsum4[tid] = make_float4(0.f, 0.f, 0.f, 0.f);
    if (tid < N_GRAPHS / 4)      gcnt4[tid] = make_float4(0.f, 0.f, 0.f, 0.f);
}

// pool_sum + pool_cnt merged: lane c8==0 also counts the node
__global__ void pool_all(const bf16* __restrict__ h, const int* __restrict__ batch,
                         float* __restrict__ gsum, float* __restrict__ gcnt) {
    int tid = blockIdx.x * blockDim.x + threadIdx.x;
    if (tid >= N_NODES * 32) return;
    int n  = tid >> 5;
    int c8 = (tid & 31) << 3;
    int g  = batch[n];
    uint4 raw = *(const uint4*)&h[(size_t)n * DD + c8];
    const bf162* p2 = (const bf162*)&raw;
    float2 f0 = __bfloat1622float2(p2[0]);
    float2 f1 = __bfloat1622float2(p2[1]);
    float2 f2 = __bfloat1622float2(p2[2]);
    float2 f3 = __bfloat1622float2(p2[3]);
    red_add_v4(&gsum[g * DD + c8],     make_float4(f0.x, f0.y, f1.x, f1.y));
    red_add_v4(&gsum[g * DD + c8 + 4], make_float4(f2.x, f2.y, f3.x, f3.y));
    if (c8 == 0) atomicAdd(&gcnt[g], 1.f);
}

__global__ void classifier(const float* __restrict__ gsum, const float* __restrict__ gcnt,
                           const float* __restrict__ w1, const float* __restrict__ b1,
                           const float* __restrict__ w2, const float* __restrict__ b2,
                           float* __restrict__ out) {
    int g = blockIdx.x, t = threadIdx.x;   // 128 threads
    __shared__ float repr[DD];
    __shared__ float red[HID];
    float inv = 1.f / fmaxf(gcnt[g], 1.f);
    repr[t]       = gsum[g * DD + t] * inv;
    repr[t + HID] = gsum[g * DD + t + HID] * inv;
    __syncthreads();
    float acc = b1[t];
    const float* w = w1 + t * DD;
#pragma unroll 8
    for (int k = 0; k < DD; k++) acc += repr[k] * w[k];
    red[t] = fmaxf(acc, 0.f) * w2[t];
    __syncthreads();
    for (int s = 64; s > 0; s >>= 1) {
        if (t < s) red[t] += red[t + s];
        __syncthreads();
    }
    if (t == 0) out[g] = 1.f / (1.f + expf(-(red[0] + b2[0])));
}

// ---------------- launch -----------------------------------------------------
static void run_gemm(const bf16* A, const bf16* B, const float* bias, bf16* C,
                     int M, int N, int K, int lda, int ldb, int ldc) {
    dim3 grid(N / BN, (M + BM - 1) / BM);
    gemm_bf<<<grid, GT, GEMM_SMEM>>>(A, B, bias, C, M, K, lda, ldb, ldc);
}

extern "C" void kernel_launch(void* const* d_in, const int* in_sizes, int n_in,
                              void* d_out, int out_size) {
    const float* x      = (const float*)d_in[0];
    const float* lin_w  = (const float*)d_in[1];
    const float* lin_b  = (const float*)d_in[2];
    const float* ggnn_w = (const float*)d_in[3];
    const float* w_ih   = (const float*)d_in[4];
    const float* w_hh   = (const float*)d_in[5];
    const float* b_ih   = (const float*)d_in[6];
    const float* b_hh   = (const float*)d_in[7];
    const float* cls_w1 = (const float*)d_in[8];
    const float* cls_b1 = (const float*)d_in[9];
    const float* cls_w2 = (const float*)d_in[10];
    const float* cls_b2 = (const float*)d_in[11];
    const int* edge_index = (const int*)d_in[12];
    const int* batch      = (const int*)d_in[13];
    float* out = (float*)d_out;

    bf16 *hb, *aggb, *ghb, *gib, *xb, *linwb, *wihb, *whhb, *gwb, *Qb;
    float *gsum, *gcnt;
    int *deg, *start, *fill, *srcl, *part;
    cudaGetSymbolAddress((void**)&hb,    g_hb);
    cudaGetSymbolAddress((void**)&aggb,  g_aggb);
    cudaGetSymbolAddress((void**)&ghb,   g_ghb);
    cudaGetSymbolAddress((void**)&gib,   g_gib);
    cudaGetSymbolAddress((void**)&xb,    g_xb);
    cudaGetSymbolAddress((void**)&linwb, g_linwb);
    cudaGetSymbolAddress((void**)&wihb,  g_wihb);
    cudaGetSymbolAddress((void**)&whhb,  g_whhb);
    cudaGetSymbolAddress((void**)&gwb,   g_gwb);
    cudaGetSymbolAddress((void**)&Qb,    g_Qb);
    cudaGetSymbolAddress((void**)&gsum,  g_gsum);
    cudaGetSymbolAddress((void**)&gcnt,  g_gcnt);
    cudaGetSymbolAddress((void**)&deg,   g_deg);
    cudaGetSymbolAddress((void**)&start, g_start);
    cudaGetSymbolAddress((void**)&fill,  g_fill);
    cudaGetSymbolAddress((void**)&srcl,  g_srcl);
    cudaGetSymbolAddress((void**)&part,  g_part);

    cudaFuncSetAttribute(gemm_bf,   cudaFuncAttributeMaxDynamicSharedMemorySize, GEMM_SMEM);
    cudaFuncSetAttribute(gh_gather, cudaFuncAttributeMaxDynamicSharedMemorySize, GEMM_SMEM);

    // ---- CSR build (parallel 3-phase scan) ----
    zero_int<<<(N_NODES + 255) / 256, 256>>>(deg, N_NODES);
    hist_k<<<(N_EDGES + 255) / 256, 256>>>(edge_index, deg);
    scan_part<<<SCB, 256>>>(deg, part);
    scan_base<<<1, 512>>>(part);
    scan_final<<<SCB, 256>>>(deg, part, start, fill);
    fill_k<<<(N_EDGES + 255) / 256, 256>>>(edge_index, fill, srcl);

    // ---- single batched fp32 -> bf16 conversion ----
    convert_all<<<(CV_TOTAL + 255) / 256, 256>>>(x, lin_w, w_ih, w_hh, ggnn_w,
                                                 xb, linwb, wihb, whhb, gwb);

    // Q[j, s*256+p] = sum_k w_ih[j,k] * ggnn_w[s][p,k]
    run_gemm(wihb, gwb, nullptr, Qb, 3 * DD, STEPS * DD, DD, DD, DD, STEPS * DD);
    // h = x @ lin_w^T + lin_b
    run_gemm(xb, linwb, lin_b, hb, N_NODES, DD, EMB, EMB, EMB, DD);

    for (int s = 0; s < STEPS; s++) {
        // gh = h @ w_hh^T + b_hh  overlapped with  agg[n] = sum_{e: dst=n} h[src]
        gh_gather<<<TOT, GT, GEMM_SMEM>>>(hb, whhb, b_hh, ghb, start, deg, srcl, aggb);
        // gi = agg @ Q_s^T + b_ih
        run_gemm(aggb, Qb + s * DD, b_ih, gib, N_NODES, 3 * DD, DD, DD, STEPS * DD, 3 * DD);
        gru_update<<<(N_NODES * 32 + 255) / 256, 256>>>(gib, ghb, hb);
    }

    zero_pool<<<(N_GRAPHS * DD / 4 + 255) / 256, 256>>>((float4*)gsum, (float4*)gcnt);
    pool_all<<<(N_NODES * 32 + 255) / 256, 256>>>(hb, batch, gsum, gcnt);
    classifier<<<N_GRAPHS, HID>>>(gsum, gcnt, cls_w1, cls_b1, cls_w2, cls_b2, out);
}